// round 11
// baseline (speedup 1.0000x reference)
#include <cuda_runtime.h>
#include <cuda_bf16.h>

#define KMAX 8
#define NT 512
#define NWARP (NT / 32)
#define FULLM 0xffffffffu

// out[b,d] = sum_j (1/(c_j*k)) * sum_{t: seqs[b,t]==aval_j, t<L, t+j+1<L} emb[b,t+j+1,d]
//   L      = nonzero prefix length of seqs[b,:] (right-padded, valid ids >= 1)
//   aval_j = seqs[b, max(L-1-j, 0)]
//   c_j    = # of t in [0,L) with seqs[b,t]==aval_j
// FAST PATH: requires S == 4*NT. One CTA per batch row; results fired straight
// into out via no-return global atomics (out zeroed by this CTA, ordered by bar 1).
__global__ __launch_bounds__(NT)
void wave_fast_kernel(const int* __restrict__ seqs,
                      const float* __restrict__ emb,
                      const int* __restrict__ kptr,
                      float* __restrict__ out,
                      int S, int D) {
    const int b    = blockIdx.x;
    const int tid  = threadIdx.x;
    const int lane = tid & 31;
    const int warp = tid >> 5;

    __shared__ int warpMin[NWARP];
    __shared__ int cnt[KMAX];

    int k = *kptr;
    if (k > KMAX) k = KMAX;
    if (k < 1) k = 1;

    float* ob = out + (size_t)b * D;
    for (int d = tid; d < D; d += NT) ob[d] = 0.0f;     // init output (poisoned)
    if (tid < KMAX) cnt[tid] = 0;

    // ---- load 4 ints/thread (one LDG.128), boundary detect ----
    const int* seq = seqs + (size_t)b * S;
    const int base = tid << 2;
    int4 a0 = ((const int4*)(seq + base))[0];
    int vv[4];
    vv[0] = a0.x; vv[1] = a0.y; vv[2] = a0.z; vv[3] = a0.w;

    int nxt = __shfl_down_sync(FULLM, vv[0], 1);
    if (lane == 31) nxt = (base + 4 < S) ? __ldg(seq + base + 4) : 0;

    unsigned cand = (unsigned)S;
    if (base == 0 && vv[0] == 0) cand = 0;
    #pragma unroll
    for (int i = 0; i < 3; i++)
        if (vv[i] != 0 && vv[i + 1] == 0) cand = (unsigned)(base + i + 1);
    if (vv[3] != 0 && nxt == 0) cand = (unsigned)(base + 4);

    cand = __reduce_min_sync(FULLM, cand);              // single REDUX.MIN
    if (lane == 0) warpMin[warp] = (int)cand;
    __syncthreads();                                    // BAR 1 (orders ob zeroing too)

    // cross-warp min: lane-indexed LDS + one REDUX.MIN
    unsigned lm = (unsigned)warpMin[lane & (NWARP - 1)];
    const int L = (int)__reduce_min_sync(FULLM, lm);

    // ---- anchors: per-warp redundant fetch (L1-hot), broadcast to registers ----
    int my_aval = 0;
    if (lane < k) {
        int a = L - 1 - lane;
        my_aval = __ldg(seq + (a > 0 ? a : 0));
    }
    int av[KMAX];
    #pragma unroll
    for (int j = 0; j < KMAX; j++) av[j] = __shfl_sync(FULLM, my_aval, j);

    // ---- single mask pass; packed 8-bit popcount reduction (2 REDUX total) ----
    unsigned mk[KMAX];
    #pragma unroll
    for (int j = 0; j < KMAX; j++) {
        mk[j] = 0;
        if (j < k) {
            #pragma unroll
            for (int i = 0; i < 4; i++)
                if (vv[i] == av[j] && vv[i] != 0) mk[j] |= (1u << i);
        }
    }
    unsigned pc0 = (unsigned)__popc(mk[0])        | ((unsigned)__popc(mk[1]) << 8)
                 | ((unsigned)__popc(mk[2]) << 16) | ((unsigned)__popc(mk[3]) << 24);
    unsigned pc1 = (unsigned)__popc(mk[4])        | ((unsigned)__popc(mk[5]) << 8)
                 | ((unsigned)__popc(mk[6]) << 16) | ((unsigned)__popc(mk[7]) << 24);
    pc0 = __reduce_add_sync(FULLM, pc0);                // per-j warp totals <= 128: no carry
    pc1 = __reduce_add_sync(FULLM, pc1);
    if (lane == 0) {
        #pragma unroll
        for (int j = 0; j < 4; j++) {
            unsigned c = (pc0 >> (8 * j)) & 0xffu;
            if (c) atomicAdd(&cnt[j], (int)c);
        }
        #pragma unroll
        for (int j = 0; j < 4; j++) {
            unsigned c = (pc1 >> (8 * j)) & 0xffu;
            if (c) atomicAdd(&cnt[j + 4], (int)c);
        }
    }
    __syncthreads();                                    // BAR 2

    // ---- gather pass: scaled, fire-and-forget global atomics ----
    const float* eb = emb + (size_t)b * S * D;
    const float fk = (float)k;
    #pragma unroll
    for (int j = 0; j < KMAX; j++) {
        if (j >= k) break;
        unsigned tmask = __ballot_sync(FULLM, mk[j] != 0);
        if (!tmask) continue;
        const float scale = __fdividef(1.0f, (float)cnt[j] * fk);
        while (tmask) {
            const int src = __ffs(tmask) - 1;
            tmask &= tmask - 1;
            unsigned em = __shfl_sync(FULLM, mk[j], src);
            const int sbase = (((warp << 5) + src) << 2) + j + 1;
            while (em) {
                const int i = __ffs(em) - 1;
                em &= em - 1;
                const int s = sbase + i;
                if (s < L) {
                    const float* row = eb + (size_t)s * D;
                    if (D == 64) {                      // bench shape: fully unrolled
                        float2 e2 = *(const float2*)(row + 2 * lane);
                        atomicAdd(&ob[2 * lane],     e2.x * scale);
                        atomicAdd(&ob[2 * lane + 1], e2.y * scale);
                    } else if ((D & 1) == 0) {
                        for (int d = 2 * lane; d < D; d += 64) {
                            float2 e2 = *(const float2*)(row + d);
                            atomicAdd(&ob[d],     e2.x * scale);
                            atomicAdd(&ob[d + 1], e2.y * scale);
                        }
                    } else {
                        for (int d = lane; d < D; d += 32)
                            atomicAdd(&ob[d], row[d] * scale);
                    }
                }
            }
        }
    }
    // no epilogue, no final barrier — REDG atomics drain before kernel completion
}

// ============================ FALLBACK (any S) ==============================
__global__ __launch_bounds__(256)
void wave_fallback_kernel(const int* __restrict__ seqs,
                          const float* __restrict__ emb,
                          const int* __restrict__ kptr,
                          float* __restrict__ out,
                          int S, int D) {
    const int b    = blockIdx.x;
    const int tid  = threadIdx.x;
    const int lane = tid & 31;
    const int warp = tid >> 5;

    extern __shared__ int smem[];
    float* acc  = (float*)smem;                 // KMAX*D
    int*   sseq = smem + KMAX * D;              // S ints

    __shared__ int cnt[KMAX];
    __shared__ int sLsh;

    const int* seq = seqs + (size_t)b * S;
    int k = *kptr;
    if (k > KMAX) k = KMAX;
    if (k < 1) k = 1;

    if (tid == 0) sLsh = S;
    if (tid < KMAX) cnt[tid] = 0;
    for (int i = tid; i < KMAX * D; i += 256) acc[i] = 0.0f;
    for (int i = tid; i < S; i += 256) sseq[i] = seq[i];
    __syncthreads();
    for (int i = tid; i < S; i += 256) {
        int v = sseq[i];
        if (i == 0 && v == 0) atomicMin(&sLsh, 0);
        if (v != 0 && (i + 1 == S || sseq[i + 1] == 0)) atomicMin(&sLsh, i + 1);
    }
    __syncthreads();
    const int L = sLsh;
    int my_aval = 0;
    if (lane < k) {
        int a = L - 1 - lane;
        my_aval = sseq[a > 0 ? a : 0];
    }
    const float* eb = emb + (size_t)b * S * D;
    for (int t0 = warp * 32; t0 < L; t0 += 256) {
        const int t = t0 + lane;
        const int v = (t < L) ? sseq[t] : 0;
        for (int j = 0; j < k; j++) {
            const int av = __shfl_sync(FULLM, my_aval, j);
            unsigned m = __ballot_sync(FULLM, v == av && v != 0);
            if (!m) continue;
            if (lane == 0) atomicAdd(&cnt[j], __popc(m));
            float* aj = acc + j * D;
            while (m) {
                const int l = __ffs(m) - 1;
                m &= m - 1;
                const int s = t0 + l + j + 1;
                if (s < L) {
                    const float* row = eb + (size_t)s * D;
                    for (int d = lane; d < D; d += 32) atomicAdd(&aj[d], row[d]);
                }
            }
        }
    }
    __syncthreads();
    const float invk = 1.0f / (float)k;
    for (int d = tid; d < D; d += 256) {
        float s = 0.0f;
        for (int j = 0; j < k; j++) {
            int c = cnt[j];
            if (c > 0) s += acc[j * D + d] / (float)c;
        }
        out[(size_t)b * D + d] = s * invk;
    }
}

extern "C" void kernel_launch(void* const* d_in, const int* in_sizes, int n_in,
                              void* d_out, int out_size) {
    const int*   seqs = (const int*)d_in[0];
    const float* emb  = (const float*)d_in[1];
    const int*   kptr = (const int*)d_in[2];
    float*       out  = (float*)d_out;

    const int n_seq = in_sizes[0];   // B*S
    const int n_emb = in_sizes[1];   // B*S*D
    const int D = n_emb / n_seq;
    const int B = out_size / D;
    const int S = n_seq / B;

    if (S == NT * 4) {
        wave_fast_kernel<<<B, NT>>>(seqs, emb, kptr, out, S, D);
    } else {
        size_t shmem = (size_t)KMAX * D * sizeof(float) + (size_t)S * sizeof(int);
        wave_fallback_kernel<<<B, 256, shmem>>>(seqs, emb, kptr, out, S, D);
    }
}